// round 5
// baseline (speedup 1.0000x reference)
#include <cuda_runtime.h>

#define T_ 1024
#define B_ 128
#define L_ 128
#define STRIDE_ (B_ * L_)

typedef unsigned long long ull;

// scratch (no allocations allowed)
__device__ float g_den[B_];
__device__ float g_num[B_];

__device__ __forceinline__ ull ffma2(ull a, ull b, ull c) {
    ull d;
    asm("fma.rn.f32x2 %0, %1, %2, %3;" : "=l"(d) : "l"(a), "l"(b), "l"(c));
    return d;
}
__device__ __forceinline__ ull add2(ull a, ull b) {
    ull d;
    asm("add.rn.f32x2 %0, %1, %2;" : "=l"(d) : "l"(a), "l"(b));
    return d;
}
__device__ __forceinline__ ull pack2(float lo, float hi) {
    ull d;
    asm("mov.b64 %0, {%1, %2};" : "=l"(d) : "f"(lo), "f"(hi));
    return d;
}
__device__ __forceinline__ float2 unpack2(ull v) {
    float2 f;
    asm("mov.b64 {%0, %1}, %2;" : "=f"(f.x), "=f"(f.y) : "l"(v));
    return f;
}

// ---------------------------------------------------------------------------
// Denominator. One block (128 thr) per batch b; thread j owns state/column j.
// expT column j lives in 64 packed registers. u vector exchanged via smem
// (broadcast LDS.128). pred stream prefetched with a depth-4 register ring
// (covers the 577-cycle DRAM latency). Renormalize by broadcast u[0] every
// 4 steps (exact for any consistent positive scale).
// ---------------------------------------------------------------------------
__global__ __launch_bounds__(L_) void crf_den_kernel(
    const float* __restrict__ pred,    // (T,B,L)
    const int*   __restrict__ mask,    // (T,B)
    const float* __restrict__ trans,   // (L,L)
    const float* __restrict__ start,   // (L)
    const float* __restrict__ endv)    // (L)
{
    const int b    = blockIdx.x;
    const int j    = threadIdx.x;
    const int lane = j & 31;
    const int w    = j >> 5;

    // exp(transitions) column j, packed in row pairs (64 x 64-bit regs)
    ull rT2[64];
#pragma unroll
    for (int k = 0; k < 64; ++k)
        rT2[k] = pack2(expf(trans[(2 * k) * L_ + j]),
                       expf(trans[(2 * k + 1) * L_ + j]));

    __shared__ __align__(16) float e_sh[2][L_];
    __shared__ int   m_sh[T_];
    __shared__ float red[4];

    // preload mask column b (one time)
#pragma unroll
    for (int t = j; t < T_; t += L_)
        m_sh[t] = mask[t * B_ + b];

    const float* pj = pred + b * L_ + j;

    float u    = __expf(start[j] + pj[0]);   // t = 0
    float logZ = 0.0f;
    int   buf  = 0;
    e_sh[0][j] = u;
    __syncthreads();

    // depth-4 prediction prefetch ring
    float pr0 = pj[(size_t)1 << 14];
    float pr1 = pj[(size_t)2 << 14];
    float pr2 = pj[(size_t)3 << 14];
    float pr3 = pj[(size_t)4 << 14];

#define PLOAD(tl) (((tl) < T_) ? pj[(size_t)(tl) << 14] : 0.0f)

#define STEP(t_, pcur_, RN_)                                                  \
    do {                                                                      \
        const int   mk = m_sh[t_];                                            \
        float inv_m = 1.0f;                                                   \
        if (RN_) {                                                            \
            const float mval = e_sh[buf][0];                                  \
            logZ += __logf(mval);                                             \
            inv_m = 1.0f / mval;                                              \
        }                                                                     \
        const float ep = __expf(pcur_);                                       \
        const ulonglong2* ev =                                                \
            reinterpret_cast<const ulonglong2*>(&e_sh[buf][0]);               \
        ull c0 = 0ull, c1 = 0ull, c2 = 0ull, c3 = 0ull;                       \
        ull c4 = 0ull, c5 = 0ull, c6 = 0ull, c7 = 0ull;                       \
        _Pragma("unroll")                                                     \
        for (int i = 0; i < 8; ++i) {                                         \
            ulonglong2 x = ev[4 * i];                                         \
            ulonglong2 y = ev[4 * i + 1];                                     \
            ulonglong2 z = ev[4 * i + 2];                                     \
            ulonglong2 q = ev[4 * i + 3];                                     \
            c0 = ffma2(x.x, rT2[8 * i + 0], c0);                              \
            c1 = ffma2(x.y, rT2[8 * i + 1], c1);                              \
            c2 = ffma2(y.x, rT2[8 * i + 2], c2);                              \
            c3 = ffma2(y.y, rT2[8 * i + 3], c3);                              \
            c4 = ffma2(z.x, rT2[8 * i + 4], c4);                              \
            c5 = ffma2(z.y, rT2[8 * i + 5], c5);                              \
            c6 = ffma2(q.x, rT2[8 * i + 6], c6);                              \
            c7 = ffma2(q.y, rT2[8 * i + 7], c7);                              \
        }                                                                     \
        c0 = add2(c0, c1); c2 = add2(c2, c3);                                 \
        c4 = add2(c4, c5); c6 = add2(c6, c7);                                 \
        c0 = add2(c0, c2); c4 = add2(c4, c6);                                 \
        c0 = add2(c0, c4);                                                    \
        float2 fx = unpack2(c0);                                              \
        const float part = fx.x + fx.y;                                       \
        u = (mk ? part * ep : u) * inv_m;                                     \
        buf ^= 1;                                                             \
        e_sh[buf][j] = u;                                                     \
        __syncthreads();                                                      \
    } while (0)

    // main loop: groups of 4 (t = tb..tb+3), renorm at t % 4 == 0 slot
    for (int tb = 1; tb + 3 < T_; tb += 4) {
        STEP(tb + 0, pr0, false); pr0 = PLOAD(tb + 4);
        STEP(tb + 1, pr1, false); pr1 = PLOAD(tb + 5);
        STEP(tb + 2, pr2, false); pr2 = PLOAD(tb + 6);
        STEP(tb + 3, pr3, true);  pr3 = PLOAD(tb + 7);
    }
    // epilogue: t = 1021, 1022, 1023
    STEP(T_ - 3, pr0, false);
    STEP(T_ - 2, pr1, false);
    STEP(T_ - 1, pr2, false);

#undef STEP
#undef PLOAD

    // den[b] = logZ + log( sum_j u[j] * exp(end[j]) )
    float v = u * __expf(endv[j]);
#pragma unroll
    for (int off = 16; off; off >>= 1)
        v += __shfl_xor_sync(0xffffffffu, v, off);
    if (lane == 0) red[w] = v;
    __syncthreads();
    if (j == 0) {
        float s = (red[0] + red[1]) + (red[2] + red[3]);
        g_den[b] = logZ + __logf(s);
    }
}

// ---------------------------------------------------------------------------
// Numerator: path score. One block per batch b, 256 threads stride over t.
// Targets may be int64 or int32 (JAX x64 off) — sniff at runtime.
// ---------------------------------------------------------------------------
__global__ __launch_bounds__(256) void crf_num_kernel(
    const float* __restrict__ pred,
    const void*  __restrict__ tgt_raw,
    const int*   __restrict__ mask,
    const float* __restrict__ trans,
    const float* __restrict__ start,
    const float* __restrict__ endv)
{
    const int b    = blockIdx.x;
    const int tid  = threadIdx.x;
    const int lane = tid & 31;
    const int wid  = tid >> 5;

    __shared__ int s_is64;
    if (tid == 0) {
        const unsigned int* wp = (const unsigned int*)tgt_raw;
        int is64 = 1;
#pragma unroll
        for (int k = 0; k < 32; ++k)
            if (wp[2 * k + 1] != 0u) { is64 = 0; break; }
        s_is64 = is64;
    }
    __syncthreads();
    const int is64 = s_is64;
    const long long* t64 = (const long long*)tgt_raw;
    const int*       t32 = (const int*)tgt_raw;

    float local = 0.0f;
    int   mcnt  = 0;

    for (int t = tid; t < T_; t += 256) {
        const int mk = mask[t * B_ + b];
        mcnt += mk;
        if (t >= 1 && mk) {
            const int cur = is64 ? (int)t64[t * B_ + b]       : t32[t * B_ + b];
            const int prv = is64 ? (int)t64[(t - 1) * B_ + b] : t32[(t - 1) * B_ + b];
            local += trans[prv * L_ + cur] +
                     pred[(size_t)t * STRIDE_ + b * L_ + cur];
        }
    }

    __shared__ float sf[8];
    __shared__ int   si[8];
#pragma unroll
    for (int off = 16; off; off >>= 1) {
        local += __shfl_xor_sync(0xffffffffu, local, off);
        mcnt  += __shfl_xor_sync(0xffffffffu, mcnt,  off);
    }
    if (lane == 0) { sf[wid] = local; si[wid] = mcnt; }
    __syncthreads();

    if (tid == 0) {
        float tot = 0.0f;
        int   mt  = 0;
#pragma unroll
        for (int q = 0; q < 8; ++q) { tot += sf[q]; mt += si[q]; }
        const int t0 = is64 ? (int)t64[b] : t32[b];
        float sc = start[t0] + pred[b * L_ + t0] + tot;
        const int last = mt - 1;
        const int tl = is64 ? (int)t64[last * B_ + b] : t32[last * B_ + b];
        sc += endv[tl];
        g_num[b] = sc;
    }
}

// ---------------------------------------------------------------------------
// Final: out = mean(den - num)
// ---------------------------------------------------------------------------
__global__ __launch_bounds__(B_) void crf_final_kernel(float* __restrict__ out)
{
    const int j    = threadIdx.x;
    const int lane = j & 31;
    const int wid  = j >> 5;

    float v = g_den[j] - g_num[j];
    __shared__ float red[4];
#pragma unroll
    for (int off = 16; off; off >>= 1)
        v += __shfl_xor_sync(0xffffffffu, v, off);
    if (lane == 0) red[wid] = v;
    __syncthreads();
    if (j == 0)
        out[0] = ((red[0] + red[1]) + (red[2] + red[3])) * (1.0f / (float)B_);
}

extern "C" void kernel_launch(void* const* d_in, const int* in_sizes, int n_in,
                              void* d_out, int out_size)
{
    const float* pred  = (const float*)d_in[0];
    const void*  tgt   = (const void*)d_in[1];
    const int*   mask  = (const int*)d_in[2];
    const float* trans = (const float*)d_in[3];
    const float* start = (const float*)d_in[4];
    const float* endv  = (const float*)d_in[5];
    float* out = (float*)d_out;

    crf_den_kernel<<<B_, L_>>>(pred, mask, trans, start, endv);
    crf_num_kernel<<<B_, 256>>>(pred, tgt, mask, trans, start, endv);
    crf_final_kernel<<<1, B_>>>(out);
}